// round 11
// baseline (speedup 1.0000x reference)
#include <cuda_runtime.h>
#include <cuda_bf16.h>

#define NN_MAX 100000
#define EE_MAX 1600000
#define ETOT_MAX (EE_MAX + NN_MAX)
#define NEGSLOPE 0.2f
#define EPSV 1e-16f
#define SCHUNK 512

// ---------------- scratch (static device allocations) ----------------
__device__ int                 g_cnt[NN_MAX];
__device__ int                 g_rowptr[NN_MAX + 1];
__device__ int                 g_cur[NN_MAX];
__device__ int2                g_pc[ETOT_MAX];     // CSR pos -> (src node, original edge id)
__device__ int                 g_bsum[(NN_MAX + SCHUNK - 1) / SCHUNK + 1];
__device__ __align__(16) unsigned g_xp[NN_MAX * 128];  // packed bf16(hi|lo) of x
__device__ __align__(16) unsigned g_hp[NN_MAX * 64];   // packed bf16(hi|lo) of relu(out1)
__device__ __align__(16) float g_xl[NN_MAX * 64];
__device__ __align__(16) float g_xr[NN_MAX * 64];
__device__ float4              g_sc[ETOT_MAX];     // per CSR pos: exp(score) per head

// ---------------- bf16 split-pack helpers ----------------
__device__ __forceinline__ unsigned packbf(float f) {
    __nv_bfloat16 h = __float2bfloat16(f);
    float r = f - __bfloat162float(h);
    __nv_bfloat16 l = __float2bfloat16(r);
    return (unsigned)__bfloat16_as_ushort(h) | ((unsigned)__bfloat16_as_ushort(l) << 16);
}

__device__ __forceinline__ void cpasync16(void* smem_dst, const void* gsrc) {
    unsigned d = (unsigned)__cvta_generic_to_shared(smem_dst);
    asm volatile("cp.async.cg.shared.global [%0], [%1], 16;" :: "r"(d), "l"(gsrc) : "memory");
}

__device__ __forceinline__ void mma16(float* c, unsigned a0, unsigned a1,
                                      unsigned a2, unsigned a3,
                                      unsigned b0, unsigned b1) {
    asm("mma.sync.aligned.m16n8k16.row.col.f32.bf16.bf16.f32 "
        "{%0,%1,%2,%3},{%4,%5,%6,%7},{%8,%9},{%0,%1,%2,%3};"
        : "+f"(c[0]), "+f"(c[1]), "+f"(c[2]), "+f"(c[3])
        : "r"(a0), "r"(a1), "r"(a2), "r"(a3), "r"(b0), "r"(b1));
}

// ---------------- CSR build ----------------
__global__ void k_zero(int n) {
    int i = blockIdx.x * blockDim.x + threadIdx.x;
    if (i < n) g_cnt[i] = 0;
}

__global__ void k_count(const int* __restrict__ ei, int E, int etot) {
    int e = blockIdx.x * blockDim.x + threadIdx.x;
    if (e >= etot) return;
    int d = (e < E) ? ei[E + e] : (e - E);
    atomicAdd(&g_cnt[d], 1);
}

// prepack x into hi|lo packed words (streaming, bandwidth-bound)
__global__ void k_pack(const float* __restrict__ x, int total4) {
    int i = blockIdx.x * blockDim.x + threadIdx.x;
    if (i >= total4) return;
    float4 v = ((const float4*)x)[i];
    ((uint4*)g_xp)[i] = make_uint4(packbf(v.x), packbf(v.y), packbf(v.z), packbf(v.w));
}

__global__ void k_scanA(int n) {
    int idx = blockIdx.x * SCHUNK + threadIdx.x;
    int v = (idx < n) ? g_cnt[idx] : 0;
    __shared__ int wsum[16];
    int lane = threadIdx.x & 31, wid = threadIdx.x >> 5;
    int s = v;
    #pragma unroll
    for (int off = 1; off < 32; off <<= 1) {
        int t = __shfl_up_sync(0xffffffffu, s, off);
        if (lane >= off) s += t;
    }
    if (lane == 31) wsum[wid] = s;
    __syncthreads();
    if (threadIdx.x == 0) {
        int tot = 0;
        #pragma unroll
        for (int w = 0; w < 16; w++) tot += wsum[w];
        g_bsum[blockIdx.x] = tot;
    }
}

__global__ void k_scanB(int nb, int n) {
    __shared__ int wsum[8];
    int lane = threadIdx.x & 31, wid = threadIdx.x >> 5;
    int v = (threadIdx.x < nb) ? g_bsum[threadIdx.x] : 0;
    int incl = v;
    #pragma unroll
    for (int off = 1; off < 32; off <<= 1) {
        int t = __shfl_up_sync(0xffffffffu, incl, off);
        if (lane >= off) incl += t;
    }
    if (lane == 31) wsum[wid] = incl;
    __syncthreads();
    if (wid == 0 && lane < 8) {
        int s = wsum[lane];
        #pragma unroll
        for (int off = 1; off < 8; off <<= 1) {
            int t = __shfl_up_sync(0xffu, s, off);
            if (lane >= off) s += t;
        }
        wsum[lane] = s;
    }
    __syncthreads();
    int woff = (wid == 0) ? 0 : wsum[wid - 1];
    int excl = woff + incl - v;
    if (threadIdx.x < nb) g_bsum[threadIdx.x] = excl;
    if (threadIdx.x == nb - 1) g_rowptr[n] = excl + v;
}

__global__ void k_scanC(int n) {
    int idx = blockIdx.x * SCHUNK + threadIdx.x;
    int v = (idx < n) ? g_cnt[idx] : 0;
    __shared__ int wsum[16];
    int lane = threadIdx.x & 31, wid = threadIdx.x >> 5;
    int incl = v;
    #pragma unroll
    for (int off = 1; off < 32; off <<= 1) {
        int t = __shfl_up_sync(0xffffffffu, incl, off);
        if (lane >= off) incl += t;
    }
    if (lane == 31) wsum[wid] = incl;
    __syncthreads();
    if (wid == 0 && lane < 16) {
        int s = wsum[lane];
        #pragma unroll
        for (int off = 1; off < 16; off <<= 1) {
            int t = __shfl_up_sync(0xffffu, s, off);
            if (lane >= off) s += t;
        }
        wsum[lane] = s;
    }
    __syncthreads();
    int woff = (wid == 0) ? 0 : wsum[wid - 1];
    int excl = g_bsum[blockIdx.x] + woff + incl - v;
    if (idx < n) { g_rowptr[idx] = excl; g_cur[idx] = excl; }
}

__global__ void k_scatter(const int* __restrict__ ei, int E, int etot) {
    int e = blockIdx.x * blockDim.x + threadIdx.x;
    if (e >= etot) return;
    int s, d;
    if (e < E) { s = ei[e]; d = ei[E + e]; }
    else       { s = d = e - E; }
    int pos = atomicAdd(&g_cur[d], 1);
    g_pc[pos] = make_int2(s, e);
}

// ---- PERSISTENT fused dual GEMM on bf16 tensor cores -------------------
template <int K>
__global__ void __launch_bounds__(256)
k_gemm_bf(const unsigned* __restrict__ xp,
          const float* __restrict__ Wl, const float* __restrict__ bl,
          const float* __restrict__ Wr, const float* __restrict__ br,
          int nrows) {
    constexpr int LDA = K + 4;
    constexpr int LDW = 136;
    extern __shared__ unsigned smu[];
    unsigned* sX = smu;              // 64 * LDA packed words
    unsigned* sW = smu + 64 * LDA;   // K * LDW  (halves: 0-63 = Wl, 64-127 = Wr)

    int tid = threadIdx.x;

    for (int i = tid; i < K * 64; i += 256) {
        int k = i >> 6, col6 = i & 63;
        int nt = col6 >> 3, rgc = col6 & 7;
        int coff = (nt >> 2) * 32 + rgc * 4 + (nt & 3);
        sW[k * LDW + coff]      = packbf(Wl[k * 64 + col6]);
        sW[k * LDW + 64 + coff] = packbf(Wr[k * 64 + col6]);
    }

    int warp = tid >> 5, lane = tid & 31;
    int wm = warp >> 1, wn = warp & 1;
    int rg = lane >> 2, tg = lane & 3;
    constexpr int KV = K / 4;

    const unsigned* sxa = sX + (wm * 16 + rg) * LDA + tg;
    const unsigned* swb = sW + tg * LDW + wn * 64 + rg * 4;
    const float* bsrc = wn ? br : bl;
    float* dst = wn ? g_xr : g_xl;

    int ntiles = (nrows + 63) >> 6;
    for (int tile = blockIdx.x; tile < ntiles; tile += gridDim.x) {
        int blockRow = tile << 6;

        __syncthreads();
        for (int i = tid; i < 64 * KV; i += 256) {
            int r = i / KV, c = i % KV;
            int row = blockRow + r;
            if (row < nrows)
                cpasync16(&sX[r * LDA + c * 4], &xp[(size_t)row * K + c * 4]);
            else
                *(uint4*)&sX[r * LDA + c * 4] = make_uint4(0u, 0u, 0u, 0u);
        }
        asm volatile("cp.async.commit_group;" ::: "memory");
        asm volatile("cp.async.wait_group 0;" ::: "memory");
        __syncthreads();

        float acc[32];
        #pragma unroll
        for (int i = 0; i < 32; i++) acc[i] = 0.f;

        #pragma unroll 2
        for (int k0 = 0; k0 < K; k0 += 8) {
            unsigned a0 = sxa[k0];
            unsigned a1 = sxa[8 * LDA + k0];
            unsigned a2 = sxa[k0 + 4];
            unsigned a3 = sxa[8 * LDA + k0 + 4];
            unsigned h0 = __byte_perm(a0, 0u, 0x1010);
            unsigned h1 = __byte_perm(a1, 0u, 0x1010);
            unsigned h2 = __byte_perm(a2, 0u, 0x1010);
            unsigned h3 = __byte_perm(a3, 0u, 0x1010);
            unsigned l0 = __byte_perm(a0, 0u, 0x4432);
            unsigned l1 = __byte_perm(a1, 0u, 0x4432);
            unsigned l2 = __byte_perm(a2, 0u, 0x4432);
            unsigned l3 = __byte_perm(a3, 0u, 0x4432);
            #pragma unroll
            for (int ntg = 0; ntg < 2; ntg++) {
                uint4 b0 = *(const uint4*)&swb[k0 * LDW + ntg * 32];
                uint4 b1 = *(const uint4*)&swb[(k0 + 4) * LDW + ntg * 32];
                const unsigned* b0w = (const unsigned*)&b0;
                const unsigned* b1w = (const unsigned*)&b1;
                #pragma unroll
                for (int j = 0; j < 4; j++) {
                    int nt = ntg * 4 + j;
                    mma16(acc + nt * 4, h0, h1, h2, h3, b0w[j], b1w[j]);
                    mma16(acc + nt * 4, l0, l1, l2, l3, b0w[j], b1w[j]);
                }
            }
        }

        int row0 = blockRow + wm * 16 + rg;
        int row1 = row0 + 8;
        #pragma unroll
        for (int nt = 0; nt < 8; nt++) {
            int col = nt * 8 + 2 * tg;
            float2 bv = *(const float2*)&bsrc[col];
            if (row0 < nrows)
                *(float2*)&dst[(size_t)row0 * 64 + col] =
                    make_float2(acc[nt * 4 + 0] + bv.x, acc[nt * 4 + 1] + bv.y);
            if (row1 < nrows)
                *(float2*)&dst[(size_t)row1 * 64 + col] =
                    make_float2(acc[nt * 4 + 2] + bv.x, acc[nt * 4 + 3] + bv.y);
        }
    }
}

// ---- per-node edge phase, (edge,head)-parallel: lane = (edge slot, head) --
// warp = 8 edge slots x 4 heads; lane owns its head's 16 features in regs.
// No per-edge shuffles; one 3-round reduction per node at the end.
__global__ void k_node(int out_mode, float* __restrict__ outext,
                       const float* __restrict__ att, const float* __restrict__ bias,
                       float* __restrict__ alpha, int n) {
    int node = blockIdx.x * 8 + (threadIdx.x >> 5);
    if (node >= n) return;
    int lane = threadIdx.x & 31;
    int head = lane & 3;
    int sub  = lane >> 2;

    int rs = g_rowptr[node], re = g_rowptr[node + 1];

    const float4* xrp = (const float4*)&g_xr[(size_t)node * 64 + head * 16];
    float4 xr0 = xrp[0], xr1 = xrp[1], xr2 = xrp[2], xr3 = xrp[3];
    const float4* atp = (const float4*)&att[head * 16];
    float4 at0 = atp[0], at1 = atp[1], at2 = atp[2], at3 = atp[3];

    float den = 0.f;
    float4 ac0 = make_float4(0.f,0.f,0.f,0.f), ac1 = ac0, ac2 = ac0, ac3 = ac0;

    #define LR(v) ((v) > 0.f ? (v) : NEGSLOPE * (v))
    #define DOT4(m, a, t) do { \
        float _x = LR((a).x + (m).x), _y = LR((a).y + (m).y); \
        float _z = LR((a).z + (m).z), _w = LR((a).w + (m).w); \
        pp = fmaf(_x, (t).x, fmaf(_y, (t).y, fmaf(_z, (t).z, fmaf(_w, (t).w, pp)))); \
    } while (0)

    for (int pos0 = rs; pos0 < re; pos0 += 8) {
        int pos = pos0 + sub;
        bool act = pos < re;
        int src = act ? ((const int*)g_pc)[(size_t)pos << 1] : 0;
        const float4* xlp = (const float4*)&g_xl[(size_t)src * 64 + head * 16];
        float4 a0 = xlp[0], a1 = xlp[1], a2 = xlp[2], a3 = xlp[3];
        float pp = 0.f;
        DOT4(xr0, a0, at0);
        DOT4(xr1, a1, at1);
        DOT4(xr2, a2, at2);
        DOT4(xr3, a3, at3);
        float e = act ? __expf(pp) : 0.f;
        if (act) ((float*)&g_sc[pos])[head] = e;
        den += e;
        ac0.x = fmaf(e, a0.x, ac0.x); ac0.y = fmaf(e, a0.y, ac0.y);
        ac0.z = fmaf(e, a0.z, ac0.z); ac0.w = fmaf(e, a0.w, ac0.w);
        ac1.x = fmaf(e, a1.x, ac1.x); ac1.y = fmaf(e, a1.y, ac1.y);
        ac1.z = fmaf(e, a1.z, ac1.z); ac1.w = fmaf(e, a1.w, ac1.w);
        ac2.x = fmaf(e, a2.x, ac2.x); ac2.y = fmaf(e, a2.y, ac2.y);
        ac2.z = fmaf(e, a2.z, ac2.z); ac2.w = fmaf(e, a2.w, ac2.w);
        ac3.x = fmaf(e, a3.x, ac3.x); ac3.y = fmaf(e, a3.y, ac3.y);
        ac3.z = fmaf(e, a3.z, ac3.z); ac3.w = fmaf(e, a3.w, ac3.w);
    }
    #undef DOT4
    #undef LR

    // reduce den + acc[16] across the 8 lanes sharing this head (xor 4,8,16)
    #pragma unroll
    for (int mask = 4; mask <= 16; mask <<= 1) {
        den   += __shfl_xor_sync(0xffffffffu, den,   mask);
        ac0.x += __shfl_xor_sync(0xffffffffu, ac0.x, mask);
        ac0.y += __shfl_xor_sync(0xffffffffu, ac0.y, mask);
        ac0.z += __shfl_xor_sync(0xffffffffu, ac0.z, mask);
        ac0.w += __shfl_xor_sync(0xffffffffu, ac0.w, mask);
        ac1.x += __shfl_xor_sync(0xffffffffu, ac1.x, mask);
        ac1.y += __shfl_xor_sync(0xffffffffu, ac1.y, mask);
        ac1.z += __shfl_xor_sync(0xffffffffu, ac1.z, mask);
        ac1.w += __shfl_xor_sync(0xffffffffu, ac1.w, mask);
        ac2.x += __shfl_xor_sync(0xffffffffu, ac2.x, mask);
        ac2.y += __shfl_xor_sync(0xffffffffu, ac2.y, mask);
        ac2.z += __shfl_xor_sync(0xffffffffu, ac2.z, mask);
        ac2.w += __shfl_xor_sync(0xffffffffu, ac2.w, mask);
        ac3.x += __shfl_xor_sync(0xffffffffu, ac3.x, mask);
        ac3.y += __shfl_xor_sync(0xffffffffu, ac3.y, mask);
        ac3.z += __shfl_xor_sync(0xffffffffu, ac3.z, mask);
        ac3.w += __shfl_xor_sync(0xffffffffu, ac3.w, mask);
    }
    float rcp = 1.f / (den + EPSV);

    if (sub == 0) {
        const float4* bp = (const float4*)&bias[head * 16];
        float4 b0 = bp[0], b1 = bp[1], b2 = bp[2], b3 = bp[3];
        float o[16];
        o[0]=fmaxf(fmaf(ac0.x,rcp,b0.x),0.f); o[1]=fmaxf(fmaf(ac0.y,rcp,b0.y),0.f);
        o[2]=fmaxf(fmaf(ac0.z,rcp,b0.z),0.f); o[3]=fmaxf(fmaf(ac0.w,rcp,b0.w),0.f);
        o[4]=fmaxf(fmaf(ac1.x,rcp,b1.x),0.f); o[5]=fmaxf(fmaf(ac1.y,rcp,b1.y),0.f);
        o[6]=fmaxf(fmaf(ac1.z,rcp,b1.z),0.f); o[7]=fmaxf(fmaf(ac1.w,rcp,b1.w),0.f);
        o[8]=fmaxf(fmaf(ac2.x,rcp,b2.x),0.f); o[9]=fmaxf(fmaf(ac2.y,rcp,b2.y),0.f);
        o[10]=fmaxf(fmaf(ac2.z,rcp,b2.z),0.f); o[11]=fmaxf(fmaf(ac2.w,rcp,b2.w),0.f);
        o[12]=fmaxf(fmaf(ac3.x,rcp,b3.x),0.f); o[13]=fmaxf(fmaf(ac3.y,rcp,b3.y),0.f);
        o[14]=fmaxf(fmaf(ac3.z,rcp,b3.z),0.f); o[15]=fmaxf(fmaf(ac3.w,rcp,b3.w),0.f);
        if (out_mode) {
            uint4* hp = (uint4*)&g_hp[(size_t)node * 64 + head * 16];
            #pragma unroll
            for (int v = 0; v < 4; v++)
                hp[v] = make_uint4(packbf(o[v*4]), packbf(o[v*4+1]),
                                   packbf(o[v*4+2]), packbf(o[v*4+3]));
        } else {
            float4* op = (float4*)&outext[(size_t)node * 64 + head * 16];
            #pragma unroll
            for (int v = 0; v < 4; v++)
                op[v] = make_float4(o[v*4], o[v*4+1], o[v*4+2], o[v*4+3]);
        }
    }

    // alpha writeback: lane-parallel over CSR positions, float4 per edge
    float r0 = __shfl_sync(0xffffffffu, rcp, 0);
    float r1 = __shfl_sync(0xffffffffu, rcp, 1);
    float r2 = __shfl_sync(0xffffffffu, rcp, 2);
    float r3 = __shfl_sync(0xffffffffu, rcp, 3);
    for (int q = rs + lane; q < re; q += 32) {
        float4 e4 = g_sc[q];
        float4 a4 = make_float4(e4.x * r0, e4.y * r1, e4.z * r2, e4.w * r3);
        *(float4*)&alpha[(size_t)g_pc[q].y * 4] = a4;
    }
}

// ---------------- launch ----------------
extern "C" void kernel_launch(void* const* d_in, const int* in_sizes, int n_in,
                              void* d_out, int out_size) {
    const float* x     = (const float*)d_in[0];
    const int*   ei    = (const int*)d_in[1];
    const float* Wl1   = (const float*)d_in[2];
    const float* bl1   = (const float*)d_in[3];
    const float* Wr1   = (const float*)d_in[4];
    const float* br1   = (const float*)d_in[5];
    const float* att1  = (const float*)d_in[6];
    const float* bias1 = (const float*)d_in[7];
    const float* Wl2   = (const float*)d_in[8];
    const float* bl2   = (const float*)d_in[9];
    const float* Wr2   = (const float*)d_in[10];
    const float* br2   = (const float*)d_in[11];
    const float* att2  = (const float*)d_in[12];
    const float* bias2 = (const float*)d_in[13];

    int n    = in_sizes[0] / 128;  // 100000
    int E    = in_sizes[1] / 2;    // 1600000
    int etot = E + n;              // 1700000
    int nb   = (n + SCHUNK - 1) / SCHUNK;

    float* out    = (float*)d_out;
    float* outh   = out;
    float* alpha1 = out + (size_t)n * 64;
    float* alpha2 = alpha1 + (size_t)etot * 4;

    cudaFuncSetAttribute(k_gemm_bf<128>, cudaFuncAttributeMaxDynamicSharedMemorySize, 103424);
    cudaFuncSetAttribute(k_gemm_bf<64>,  cudaFuncAttributeMaxDynamicSharedMemorySize, 52224);

    unsigned* d_xp; cudaGetSymbolAddress((void**)&d_xp, g_xp);
    unsigned* d_hp; cudaGetSymbolAddress((void**)&d_hp, g_hp);

    int total4 = n * 128 / 4;

    k_zero<<<(n + 511) / 512, 512>>>(n);
    k_count<<<(etot + 511) / 512, 512>>>(ei, E, etot);
    k_pack<<<(total4 + 511) / 512, 512>>>(x, total4);
    k_gemm_bf<128><<<296, 256, 103424>>>(d_xp, Wl1, bl1, Wr1, br1, n);  // 4th -> profiled
    k_scanA<<<nb, SCHUNK>>>(n);
    k_scanB<<<1, 256>>>(nb, n);
    k_scanC<<<nb, SCHUNK>>>(n);
    k_scatter<<<(etot + 511) / 512, 512>>>(ei, E, etot);

    // layer 1 edge phase (writes packed h)
    k_node<<<(n + 7) / 8, 256>>>(1, nullptr, att1, bias1, alpha1, n);

    // layer 2 (input = packed h)
    k_gemm_bf<64><<<444, 256, 52224>>>(d_hp, Wl2, bl2, Wr2, br2, n);
    k_node<<<(n + 7) / 8, 256>>>(0, outh, att2, bias2, alpha2, n);
}

// round 12
// speedup vs baseline: 1.1258x; 1.1258x over previous
#include <cuda_runtime.h>
#include <cuda_bf16.h>

#define NN_MAX 100000
#define EE_MAX 1600000
#define ETOT_MAX (EE_MAX + NN_MAX)
#define NEGSLOPE 0.2f
#define EPSV 1e-16f
#define SCHUNK 512

// ---------------- scratch (static device allocations) ----------------
__device__ int                 g_cnt[NN_MAX];
__device__ int                 g_rowptr[NN_MAX + 1];
__device__ int                 g_cur[NN_MAX];
__device__ int2                g_pc[ETOT_MAX];     // CSR pos -> (src node, original edge id)
__device__ int                 g_bsum[(NN_MAX + SCHUNK - 1) / SCHUNK + 1];
__device__ __align__(16) unsigned g_xp[NN_MAX * 128];  // packed bf16(hi|lo) of x
__device__ __align__(16) unsigned g_hp[NN_MAX * 64];   // packed bf16(hi|lo) of relu(out1)
__device__ __align__(16) float g_xl[NN_MAX * 64];
__device__ __align__(16) float g_xr[NN_MAX * 64];
__device__ float4              g_sc[ETOT_MAX];     // per CSR pos: exp(score) per head

// ---------------- bf16 split-pack helpers ----------------
__device__ __forceinline__ unsigned packbf(float f) {
    __nv_bfloat16 h = __float2bfloat16(f);
    float r = f - __bfloat162float(h);
    __nv_bfloat16 l = __float2bfloat16(r);
    return (unsigned)__bfloat16_as_ushort(h) | ((unsigned)__bfloat16_as_ushort(l) << 16);
}

__device__ __forceinline__ void cpasync16(void* smem_dst, const void* gsrc) {
    unsigned d = (unsigned)__cvta_generic_to_shared(smem_dst);
    asm volatile("cp.async.cg.shared.global [%0], [%1], 16;" :: "r"(d), "l"(gsrc) : "memory");
}

__device__ __forceinline__ void mma16(float* c, unsigned a0, unsigned a1,
                                      unsigned a2, unsigned a3,
                                      unsigned b0, unsigned b1) {
    asm("mma.sync.aligned.m16n8k16.row.col.f32.bf16.bf16.f32 "
        "{%0,%1,%2,%3},{%4,%5,%6,%7},{%8,%9},{%0,%1,%2,%3};"
        : "+f"(c[0]), "+f"(c[1]), "+f"(c[2]), "+f"(c[3])
        : "r"(a0), "r"(a1), "r"(a2), "r"(a3), "r"(b0), "r"(b1));
}

// ---------------- CSR build ----------------
__global__ void k_zero(int n) {
    int i = blockIdx.x * blockDim.x + threadIdx.x;
    if (i < n) g_cnt[i] = 0;
}

__global__ void k_count(const int* __restrict__ ei, int E, int etot) {
    int e = blockIdx.x * blockDim.x + threadIdx.x;
    if (e >= etot) return;
    int d = (e < E) ? ei[E + e] : (e - E);
    atomicAdd(&g_cnt[d], 1);
}

// prepack x into hi|lo packed words (streaming, bandwidth-bound)
__global__ void k_pack(const float* __restrict__ x, int total4) {
    int i = blockIdx.x * blockDim.x + threadIdx.x;
    if (i >= total4) return;
    float4 v = ((const float4*)x)[i];
    ((uint4*)g_xp)[i] = make_uint4(packbf(v.x), packbf(v.y), packbf(v.z), packbf(v.w));
}

__global__ void k_scanA(int n) {
    int idx = blockIdx.x * SCHUNK + threadIdx.x;
    int v = (idx < n) ? g_cnt[idx] : 0;
    __shared__ int wsum[16];
    int lane = threadIdx.x & 31, wid = threadIdx.x >> 5;
    int s = v;
    #pragma unroll
    for (int off = 1; off < 32; off <<= 1) {
        int t = __shfl_up_sync(0xffffffffu, s, off);
        if (lane >= off) s += t;
    }
    if (lane == 31) wsum[wid] = s;
    __syncthreads();
    if (threadIdx.x == 0) {
        int tot = 0;
        #pragma unroll
        for (int w = 0; w < 16; w++) tot += wsum[w];
        g_bsum[blockIdx.x] = tot;
    }
}

__global__ void k_scanB(int nb, int n) {
    __shared__ int wsum[8];
    int lane = threadIdx.x & 31, wid = threadIdx.x >> 5;
    int v = (threadIdx.x < nb) ? g_bsum[threadIdx.x] : 0;
    int incl = v;
    #pragma unroll
    for (int off = 1; off < 32; off <<= 1) {
        int t = __shfl_up_sync(0xffffffffu, incl, off);
        if (lane >= off) incl += t;
    }
    if (lane == 31) wsum[wid] = incl;
    __syncthreads();
    if (wid == 0 && lane < 8) {
        int s = wsum[lane];
        #pragma unroll
        for (int off = 1; off < 8; off <<= 1) {
            int t = __shfl_up_sync(0xffu, s, off);
            if (lane >= off) s += t;
        }
        wsum[lane] = s;
    }
    __syncthreads();
    int woff = (wid == 0) ? 0 : wsum[wid - 1];
    int excl = woff + incl - v;
    if (threadIdx.x < nb) g_bsum[threadIdx.x] = excl;
    if (threadIdx.x == nb - 1) g_rowptr[n] = excl + v;
}

__global__ void k_scanC(int n) {
    int idx = blockIdx.x * SCHUNK + threadIdx.x;
    int v = (idx < n) ? g_cnt[idx] : 0;
    __shared__ int wsum[16];
    int lane = threadIdx.x & 31, wid = threadIdx.x >> 5;
    int incl = v;
    #pragma unroll
    for (int off = 1; off < 32; off <<= 1) {
        int t = __shfl_up_sync(0xffffffffu, incl, off);
        if (lane >= off) incl += t;
    }
    if (lane == 31) wsum[wid] = incl;
    __syncthreads();
    if (wid == 0 && lane < 16) {
        int s = wsum[lane];
        #pragma unroll
        for (int off = 1; off < 16; off <<= 1) {
            int t = __shfl_up_sync(0xffffu, s, off);
            if (lane >= off) s += t;
        }
        wsum[lane] = s;
    }
    __syncthreads();
    int woff = (wid == 0) ? 0 : wsum[wid - 1];
    int excl = g_bsum[blockIdx.x] + woff + incl - v;
    if (idx < n) { g_rowptr[idx] = excl; g_cur[idx] = excl; }
}

__global__ void k_scatter(const int* __restrict__ ei, int E, int etot) {
    int e = blockIdx.x * blockDim.x + threadIdx.x;
    if (e >= etot) return;
    int s, d;
    if (e < E) { s = ei[e]; d = ei[E + e]; }
    else       { s = d = e - E; }
    int pos = atomicAdd(&g_cur[d], 1);
    g_pc[pos] = make_int2(s, e);
}

// ---- PERSISTENT fused dual GEMM on bf16 tensor cores -------------------
template <int K>
__global__ void __launch_bounds__(256)
k_gemm_bf(const unsigned* __restrict__ xp,
          const float* __restrict__ Wl, const float* __restrict__ bl,
          const float* __restrict__ Wr, const float* __restrict__ br,
          int nrows) {
    constexpr int LDA = K + 4;
    constexpr int LDW = 136;
    extern __shared__ unsigned smu[];
    unsigned* sX = smu;              // 64 * LDA packed words
    unsigned* sW = smu + 64 * LDA;   // K * LDW  (halves: 0-63 = Wl, 64-127 = Wr)

    int tid = threadIdx.x;

    for (int i = tid; i < K * 64; i += 256) {
        int k = i >> 6, col6 = i & 63;
        int nt = col6 >> 3, rgc = col6 & 7;
        int coff = (nt >> 2) * 32 + rgc * 4 + (nt & 3);
        sW[k * LDW + coff]      = packbf(Wl[k * 64 + col6]);
        sW[k * LDW + 64 + coff] = packbf(Wr[k * 64 + col6]);
    }

    int warp = tid >> 5, lane = tid & 31;
    int wm = warp >> 1, wn = warp & 1;
    int rg = lane >> 2, tg = lane & 3;
    constexpr int KV = K / 4;

    const unsigned* sxa = sX + (wm * 16 + rg) * LDA + tg;
    const unsigned* swb = sW + tg * LDW + wn * 64 + rg * 4;
    const float* bsrc = wn ? br : bl;
    float* dst = wn ? g_xr : g_xl;

    int ntiles = (nrows + 63) >> 6;
    for (int tile = blockIdx.x; tile < ntiles; tile += gridDim.x) {
        int blockRow = tile << 6;

        __syncthreads();
        for (int i = tid; i < 64 * KV; i += 256) {
            int r = i / KV, c = i % KV;
            int row = blockRow + r;
            if (row < nrows)
                cpasync16(&sX[r * LDA + c * 4], &xp[(size_t)row * K + c * 4]);
            else
                *(uint4*)&sX[r * LDA + c * 4] = make_uint4(0u, 0u, 0u, 0u);
        }
        asm volatile("cp.async.commit_group;" ::: "memory");
        asm volatile("cp.async.wait_group 0;" ::: "memory");
        __syncthreads();

        float acc[32];
        #pragma unroll
        for (int i = 0; i < 32; i++) acc[i] = 0.f;

        #pragma unroll 2
        for (int k0 = 0; k0 < K; k0 += 8) {
            unsigned a0 = sxa[k0];
            unsigned a1 = sxa[8 * LDA + k0];
            unsigned a2 = sxa[k0 + 4];
            unsigned a3 = sxa[8 * LDA + k0 + 4];
            unsigned h0 = __byte_perm(a0, 0u, 0x1010);
            unsigned h1 = __byte_perm(a1, 0u, 0x1010);
            unsigned h2 = __byte_perm(a2, 0u, 0x1010);
            unsigned h3 = __byte_perm(a3, 0u, 0x1010);
            unsigned l0 = __byte_perm(a0, 0u, 0x4432);
            unsigned l1 = __byte_perm(a1, 0u, 0x4432);
            unsigned l2 = __byte_perm(a2, 0u, 0x4432);
            unsigned l3 = __byte_perm(a3, 0u, 0x4432);
            #pragma unroll
            for (int ntg = 0; ntg < 2; ntg++) {
                uint4 b0 = *(const uint4*)&swb[k0 * LDW + ntg * 32];
                uint4 b1 = *(const uint4*)&swb[(k0 + 4) * LDW + ntg * 32];
                const unsigned* b0w = (const unsigned*)&b0;
                const unsigned* b1w = (const unsigned*)&b1;
                #pragma unroll
                for (int j = 0; j < 4; j++) {
                    int nt = ntg * 4 + j;
                    mma16(acc + nt * 4, h0, h1, h2, h3, b0w[j], b1w[j]);
                    mma16(acc + nt * 4, l0, l1, l2, l3, b0w[j], b1w[j]);
                }
            }
        }

        int row0 = blockRow + wm * 16 + rg;
        int row1 = row0 + 8;
        #pragma unroll
        for (int nt = 0; nt < 8; nt++) {
            int col = nt * 8 + 2 * tg;
            float2 bv = *(const float2*)&bsrc[col];
            if (row0 < nrows)
                *(float2*)&dst[(size_t)row0 * 64 + col] =
                    make_float2(acc[nt * 4 + 0] + bv.x, acc[nt * 4 + 1] + bv.y);
            if (row1 < nrows)
                *(float2*)&dst[(size_t)row1 * 64 + col] =
                    make_float2(acc[nt * 4 + 2] + bv.x, acc[nt * 4 + 3] + bv.y);
        }
    }
}

// ---- per-node edge phase, hybrid layout ----------------------------------
// lane = (edge slot es=lane>>4, feature quad q=lane&15); head = q>>2.
// A warp gathers TWO full 64-feature xl rows per LDG.128 instruction.
// Score reduce = 2 SHFL per 2 edges (xor 1,2 within quad group).
// Node tail: 5 SHFL (xor 16) + epilogue STG.128 per lane.
__global__ void k_node(int out_mode, float* __restrict__ outext,
                       const float* __restrict__ att, const float* __restrict__ bias,
                       float* __restrict__ alpha, int n) {
    int node = blockIdx.x * 8 + (threadIdx.x >> 5);
    if (node >= n) return;
    int lane = threadIdx.x & 31;
    int q    = lane & 15;       // feature quad 0..15
    int es   = lane >> 4;       // edge slot 0/1
    int head = q >> 2;

    int rs = g_rowptr[node], re = g_rowptr[node + 1];

    float4 xr = *(const float4*)&g_xr[(size_t)node * 64 + q * 4];
    float4 at = *(const float4*)&att[q * 4];

    float den = 0.f;
    float4 acc = make_float4(0.f, 0.f, 0.f, 0.f);

    #pragma unroll 4
    for (int pos0 = rs; pos0 < re; pos0 += 2) {
        int pos = pos0 + es;
        bool act = pos < re;
        int src = act ? ((const int*)g_pc)[(size_t)pos << 1] : 0;
        float4 a = *(const float4*)&g_xl[(size_t)src * 64 + q * 4];
        float vx = a.x + xr.x, vy = a.y + xr.y, vz = a.z + xr.z, vw = a.w + xr.w;
        vx = vx > 0.f ? vx : NEGSLOPE * vx;
        vy = vy > 0.f ? vy : NEGSLOPE * vy;
        vz = vz > 0.f ? vz : NEGSLOPE * vz;
        vw = vw > 0.f ? vw : NEGSLOPE * vw;
        float p = fmaf(vx, at.x, fmaf(vy, at.y, fmaf(vz, at.z, vw * at.w)));
        p += __shfl_xor_sync(0xffffffffu, p, 1);
        p += __shfl_xor_sync(0xffffffffu, p, 2);    // head-group (4-lane) sum
        float e = act ? __expf(p) : 0.f;
        if (act && (q & 3) == 0) ((float*)&g_sc[pos])[head] = e;
        den += e;
        acc.x = fmaf(e, a.x, acc.x);
        acc.y = fmaf(e, a.y, acc.y);
        acc.z = fmaf(e, a.z, acc.z);
        acc.w = fmaf(e, a.w, acc.w);
    }

    // reduce across the two edge slots (xor 16)
    den   += __shfl_xor_sync(0xffffffffu, den,   16);
    acc.x += __shfl_xor_sync(0xffffffffu, acc.x, 16);
    acc.y += __shfl_xor_sync(0xffffffffu, acc.y, 16);
    acc.z += __shfl_xor_sync(0xffffffffu, acc.z, 16);
    acc.w += __shfl_xor_sync(0xffffffffu, acc.w, 16);
    float rcp = 1.f / (den + EPSV);

    if (es == 0) {
        float4 b = *(const float4*)&bias[q * 4];
        float ox = fmaxf(fmaf(acc.x, rcp, b.x), 0.f);
        float oy = fmaxf(fmaf(acc.y, rcp, b.y), 0.f);
        float oz = fmaxf(fmaf(acc.z, rcp, b.z), 0.f);
        float ow = fmaxf(fmaf(acc.w, rcp, b.w), 0.f);
        if (out_mode) {
            *(uint4*)&g_hp[(size_t)node * 64 + q * 4] =
                make_uint4(packbf(ox), packbf(oy), packbf(oz), packbf(ow));
        } else {
            *(float4*)&outext[(size_t)node * 64 + q * 4] =
                make_float4(ox, oy, oz, ow);
        }
    }

    // alpha writeback: lane-parallel over CSR positions, float4 per edge
    float r0 = __shfl_sync(0xffffffffu, rcp, 0);
    float r1 = __shfl_sync(0xffffffffu, rcp, 4);
    float r2 = __shfl_sync(0xffffffffu, rcp, 8);
    float r3 = __shfl_sync(0xffffffffu, rcp, 12);
    for (int pq = rs + lane; pq < re; pq += 32) {
        float4 e4 = g_sc[pq];
        float4 a4 = make_float4(e4.x * r0, e4.y * r1, e4.z * r2, e4.w * r3);
        *(float4*)&alpha[(size_t)g_pc[pq].y * 4] = a4;
    }
}

// ---------------- launch ----------------
extern "C" void kernel_launch(void* const* d_in, const int* in_sizes, int n_in,
                              void* d_out, int out_size) {
    const float* x     = (const float*)d_in[0];
    const int*   ei    = (const int*)d_in[1];
    const float* Wl1   = (const float*)d_in[2];
    const float* bl1   = (const float*)d_in[3];
    const float* Wr1   = (const float*)d_in[4];
    const float* br1   = (const float*)d_in[5];
    const float* att1  = (const float*)d_in[6];
    const float* bias1 = (const float*)d_in[7];
    const float* Wl2   = (const float*)d_in[8];
    const float* bl2   = (const float*)d_in[9];
    const float* Wr2   = (const float*)d_in[10];
    const float* br2   = (const float*)d_in[11];
    const float* att2  = (const float*)d_in[12];
    const float* bias2 = (const float*)d_in[13];

    int n    = in_sizes[0] / 128;  // 100000
    int E    = in_sizes[1] / 2;    // 1600000
    int etot = E + n;              // 1700000
    int nb   = (n + SCHUNK - 1) / SCHUNK;

    float* out    = (float*)d_out;
    float* outh   = out;
    float* alpha1 = out + (size_t)n * 64;
    float* alpha2 = alpha1 + (size_t)etot * 4;

    cudaFuncSetAttribute(k_gemm_bf<128>, cudaFuncAttributeMaxDynamicSharedMemorySize, 103424);
    cudaFuncSetAttribute(k_gemm_bf<64>,  cudaFuncAttributeMaxDynamicSharedMemorySize, 52224);

    unsigned* d_xp; cudaGetSymbolAddress((void**)&d_xp, g_xp);
    unsigned* d_hp; cudaGetSymbolAddress((void**)&d_hp, g_hp);

    int total4 = n * 128 / 4;

    k_zero<<<(n + 511) / 512, 512>>>(n);
    k_count<<<(etot + 511) / 512, 512>>>(ei, E, etot);
    k_pack<<<(total4 + 511) / 512, 512>>>(x, total4);
    k_gemm_bf<128><<<296, 256, 103424>>>(d_xp, Wl1, bl1, Wr1, br1, n);  // 4th -> profiled
    k_scanA<<<nb, SCHUNK>>>(n);
    k_scanB<<<1, 256>>>(nb, n);
    k_scanC<<<nb, SCHUNK>>>(n);
    k_scatter<<<(etot + 511) / 512, 512>>>(ei, E, etot);

    // layer 1 edge phase (writes packed h)
    k_node<<<(n + 7) / 8, 256>>>(1, nullptr, att1, bias1, alpha1, n);

    // layer 2 (input = packed h)
    k_gemm_bf<64><<<444, 256, 52224>>>(d_hp, Wl2, bl2, Wr2, br2, n);
    k_node<<<(n + 7) / 8, 256>>>(0, outh, att2, bias2, alpha2, n);
}

// round 13
// speedup vs baseline: 1.2795x; 1.1366x over previous
#include <cuda_runtime.h>
#include <cuda_bf16.h>

#define NN_MAX 100000
#define EE_MAX 1600000
#define ETOT_MAX (EE_MAX + NN_MAX)
#define NEGSLOPE 0.2f
#define EPSV 1e-16f
#define SCHUNK 512

// ---------------- scratch (static device allocations) ----------------
__device__ int                 g_cnt[NN_MAX];
__device__ int                 g_rowptr[NN_MAX + 1];
__device__ int                 g_cur[NN_MAX];
__device__ int2                g_pc[ETOT_MAX];     // CSR pos -> (src node, original edge id)
__device__ int                 g_bsum[(NN_MAX + SCHUNK - 1) / SCHUNK + 1];
__device__ __align__(16) unsigned g_xp[NN_MAX * 128];  // packed bf16(hi|lo) of x
__device__ __align__(16) unsigned g_hp[NN_MAX * 64];   // packed bf16(hi|lo) of relu(out1)
__device__ __align__(16) float g_xl[NN_MAX * 64];
__device__ __align__(16) float g_xr[NN_MAX * 64];
__device__ float4              g_sc[ETOT_MAX];     // per CSR pos: exp(score) per head

// ---------------- bf16 split-pack helpers ----------------
__device__ __forceinline__ unsigned packbf(float f) {
    __nv_bfloat16 h = __float2bfloat16(f);
    float r = f - __bfloat162float(h);
    __nv_bfloat16 l = __float2bfloat16(r);
    return (unsigned)__bfloat16_as_ushort(h) | ((unsigned)__bfloat16_as_ushort(l) << 16);
}

__device__ __forceinline__ void cpasync16(void* smem_dst, const void* gsrc) {
    unsigned d = (unsigned)__cvta_generic_to_shared(smem_dst);
    asm volatile("cp.async.cg.shared.global [%0], [%1], 16;" :: "r"(d), "l"(gsrc) : "memory");
}

__device__ __forceinline__ void mma16(float* c, unsigned a0, unsigned a1,
                                      unsigned a2, unsigned a3,
                                      unsigned b0, unsigned b1) {
    asm("mma.sync.aligned.m16n8k16.row.col.f32.bf16.bf16.f32 "
        "{%0,%1,%2,%3},{%4,%5,%6,%7},{%8,%9},{%0,%1,%2,%3};"
        : "+f"(c[0]), "+f"(c[1]), "+f"(c[2]), "+f"(c[3])
        : "r"(a0), "r"(a1), "r"(a2), "r"(a3), "r"(b0), "r"(b1));
}

// ---------------- CSR build ----------------
__global__ void k_count(const int* __restrict__ ei, int E, int etot) {
    int e = blockIdx.x * blockDim.x + threadIdx.x;
    if (e >= etot) return;
    int d = (e < E) ? ei[E + e] : (e - E);
    atomicAdd(&g_cnt[d], 1);
}

// prepack x into hi|lo packed words (streaming, bandwidth-bound)
__global__ void k_pack(const float* __restrict__ x, int total4) {
    int i = blockIdx.x * blockDim.x + threadIdx.x;
    if (i >= total4) return;
    float4 v = ((const float4*)x)[i];
    ((uint4*)g_xp)[i] = make_uint4(packbf(v.x), packbf(v.y), packbf(v.z), packbf(v.w));
}

__global__ void k_scanA(int n) {
    int idx = blockIdx.x * SCHUNK + threadIdx.x;
    int v = (idx < n) ? g_cnt[idx] : 0;
    __shared__ int wsum[16];
    int lane = threadIdx.x & 31, wid = threadIdx.x >> 5;
    int s = v;
    #pragma unroll
    for (int off = 1; off < 32; off <<= 1) {
        int t = __shfl_up_sync(0xffffffffu, s, off);
        if (lane >= off) s += t;
    }
    if (lane == 31) wsum[wid] = s;
    __syncthreads();
    if (threadIdx.x == 0) {
        int tot = 0;
        #pragma unroll
        for (int w = 0; w < 16; w++) tot += wsum[w];
        g_bsum[blockIdx.x] = tot;
    }
}

__global__ void k_scanB(int nb, int n) {
    __shared__ int wsum[8];
    int lane = threadIdx.x & 31, wid = threadIdx.x >> 5;
    int v = (threadIdx.x < nb) ? g_bsum[threadIdx.x] : 0;
    int incl = v;
    #pragma unroll
    for (int off = 1; off < 32; off <<= 1) {
        int t = __shfl_up_sync(0xffffffffu, incl, off);
        if (lane >= off) incl += t;
    }
    if (lane == 31) wsum[wid] = incl;
    __syncthreads();
    if (wid == 0 && lane < 8) {
        int s = wsum[lane];
        #pragma unroll
        for (int off = 1; off < 8; off <<= 1) {
            int t = __shfl_up_sync(0xffu, s, off);
            if (lane >= off) s += t;
        }
        wsum[lane] = s;
    }
    __syncthreads();
    int woff = (wid == 0) ? 0 : wsum[wid - 1];
    int excl = woff + incl - v;
    if (threadIdx.x < nb) g_bsum[threadIdx.x] = excl;
    if (threadIdx.x == nb - 1) g_rowptr[n] = excl + v;
}

__global__ void k_scanC(int n) {
    int idx = blockIdx.x * SCHUNK + threadIdx.x;
    int v = (idx < n) ? g_cnt[idx] : 0;
    __shared__ int wsum[16];
    int lane = threadIdx.x & 31, wid = threadIdx.x >> 5;
    int incl = v;
    #pragma unroll
    for (int off = 1; off < 32; off <<= 1) {
        int t = __shfl_up_sync(0xffffffffu, incl, off);
        if (lane >= off) incl += t;
    }
    if (lane == 31) wsum[wid] = incl;
    __syncthreads();
    if (wid == 0 && lane < 16) {
        int s = wsum[lane];
        #pragma unroll
        for (int off = 1; off < 16; off <<= 1) {
            int t = __shfl_up_sync(0xffffu, s, off);
            if (lane >= off) s += t;
        }
        wsum[lane] = s;
    }
    __syncthreads();
    int woff = (wid == 0) ? 0 : wsum[wid - 1];
    int excl = g_bsum[blockIdx.x] + woff + incl - v;
    if (idx < n) { g_rowptr[idx] = excl; g_cur[idx] = excl; }
}

__global__ void k_scatter(const int* __restrict__ ei, int E, int etot) {
    int e = blockIdx.x * blockDim.x + threadIdx.x;
    if (e >= etot) return;
    int s, d;
    if (e < E) { s = ei[e]; d = ei[E + e]; }
    else       { s = d = e - E; }
    int pos = atomicAdd(&g_cur[d], 1);
    g_pc[pos] = make_int2(s, e);
}

// ---- PERSISTENT fused dual GEMM on bf16 tensor cores -------------------
template <int K>
__global__ void __launch_bounds__(256)
k_gemm_bf(const unsigned* __restrict__ xp,
          const float* __restrict__ Wl, const float* __restrict__ bl,
          const float* __restrict__ Wr, const float* __restrict__ br,
          int nrows) {
    constexpr int LDA = K + 4;
    constexpr int LDW = 136;
    extern __shared__ unsigned smu[];
    unsigned* sX = smu;              // 64 * LDA packed words
    unsigned* sW = smu + 64 * LDA;   // K * LDW  (halves: 0-63 = Wl, 64-127 = Wr)

    int tid = threadIdx.x;

    for (int i = tid; i < K * 64; i += 256) {
        int k = i >> 6, col6 = i & 63;
        int nt = col6 >> 3, rgc = col6 & 7;
        int coff = (nt >> 2) * 32 + rgc * 4 + (nt & 3);
        sW[k * LDW + coff]      = packbf(Wl[k * 64 + col6]);
        sW[k * LDW + 64 + coff] = packbf(Wr[k * 64 + col6]);
    }

    int warp = tid >> 5, lane = tid & 31;
    int wm = warp >> 1, wn = warp & 1;
    int rg = lane >> 2, tg = lane & 3;
    constexpr int KV = K / 4;

    const unsigned* sxa = sX + (wm * 16 + rg) * LDA + tg;
    const unsigned* swb = sW + tg * LDW + wn * 64 + rg * 4;
    const float* bsrc = wn ? br : bl;
    float* dst = wn ? g_xr : g_xl;

    int ntiles = (nrows + 63) >> 6;
    for (int tile = blockIdx.x; tile < ntiles; tile += gridDim.x) {
        int blockRow = tile << 6;

        __syncthreads();
        for (int i = tid; i < 64 * KV; i += 256) {
            int r = i / KV, c = i % KV;
            int row = blockRow + r;
            if (row < nrows)
                cpasync16(&sX[r * LDA + c * 4], &xp[(size_t)row * K + c * 4]);
            else
                *(uint4*)&sX[r * LDA + c * 4] = make_uint4(0u, 0u, 0u, 0u);
        }
        asm volatile("cp.async.commit_group;" ::: "memory");
        asm volatile("cp.async.wait_group 0;" ::: "memory");
        __syncthreads();

        float acc[32];
        #pragma unroll
        for (int i = 0; i < 32; i++) acc[i] = 0.f;

        #pragma unroll 2
        for (int k0 = 0; k0 < K; k0 += 8) {
            unsigned a0 = sxa[k0];
            unsigned a1 = sxa[8 * LDA + k0];
            unsigned a2 = sxa[k0 + 4];
            unsigned a3 = sxa[8 * LDA + k0 + 4];
            unsigned h0 = __byte_perm(a0, 0u, 0x1010);
            unsigned h1 = __byte_perm(a1, 0u, 0x1010);
            unsigned h2 = __byte_perm(a2, 0u, 0x1010);
            unsigned h3 = __byte_perm(a3, 0u, 0x1010);
            unsigned l0 = __byte_perm(a0, 0u, 0x4432);
            unsigned l1 = __byte_perm(a1, 0u, 0x4432);
            unsigned l2 = __byte_perm(a2, 0u, 0x4432);
            unsigned l3 = __byte_perm(a3, 0u, 0x4432);
            #pragma unroll
            for (int ntg = 0; ntg < 2; ntg++) {
                uint4 b0 = *(const uint4*)&swb[k0 * LDW + ntg * 32];
                uint4 b1 = *(const uint4*)&swb[(k0 + 4) * LDW + ntg * 32];
                const unsigned* b0w = (const unsigned*)&b0;
                const unsigned* b1w = (const unsigned*)&b1;
                #pragma unroll
                for (int j = 0; j < 4; j++) {
                    int nt = ntg * 4 + j;
                    mma16(acc + nt * 4, h0, h1, h2, h3, b0w[j], b1w[j]);
                    mma16(acc + nt * 4, l0, l1, l2, l3, b0w[j], b1w[j]);
                }
            }
        }

        int row0 = blockRow + wm * 16 + rg;
        int row1 = row0 + 8;
        #pragma unroll
        for (int nt = 0; nt < 8; nt++) {
            int col = nt * 8 + 2 * tg;
            float2 bv = *(const float2*)&bsrc[col];
            if (row0 < nrows)
                *(float2*)&dst[(size_t)row0 * 64 + col] =
                    make_float2(acc[nt * 4 + 0] + bv.x, acc[nt * 4 + 1] + bv.y);
            if (row1 < nrows)
                *(float2*)&dst[(size_t)row1 * 64 + col] =
                    make_float2(acc[nt * 4 + 2] + bv.x, acc[nt * 4 + 3] + bv.y);
        }
    }
}

// ---- fused per-node edge phase, 4x unrolled edge loop (round-10 best) ----
// lane covers feature indices {2*lane, 2*lane+1}; head = lane>>3.
__global__ void k_node(int out_mode, float* __restrict__ outext,
                       const float* __restrict__ att, const float* __restrict__ bias,
                       float* __restrict__ alpha, int n) {
    int node = blockIdx.x * 8 + (threadIdx.x >> 5);
    if (node >= n) return;
    int lane = threadIdx.x & 31;
    int head = lane >> 3;

    int rs = g_rowptr[node], re = g_rowptr[node + 1];
    float2 xrv = *(const float2*)&g_xr[(size_t)node * 64 + 2 * lane];
    float2 av  = ((const float2*)att)[lane];

    float den0 = 0.f, den1 = 0.f;
    float2 acc0 = make_float2(0.f, 0.f), acc1 = make_float2(0.f, 0.f);

    int pos = rs;
    for (; pos + 4 <= re; pos += 4) {
        int2 q0 = g_pc[pos], q1 = g_pc[pos + 1], q2 = g_pc[pos + 2], q3 = g_pc[pos + 3];
        float2 x0 = *(const float2*)&g_xl[(size_t)q0.x * 64 + 2 * lane];
        float2 x1 = *(const float2*)&g_xl[(size_t)q1.x * 64 + 2 * lane];
        float2 x2 = *(const float2*)&g_xl[(size_t)q2.x * 64 + 2 * lane];
        float2 x3 = *(const float2*)&g_xl[(size_t)q3.x * 64 + 2 * lane];
        float m0x = x0.x + xrv.x, m0y = x0.y + xrv.y;
        float m1x = x1.x + xrv.x, m1y = x1.y + xrv.y;
        float m2x = x2.x + xrv.x, m2y = x2.y + xrv.y;
        float m3x = x3.x + xrv.x, m3y = x3.y + xrv.y;
        m0x = m0x > 0.f ? m0x : NEGSLOPE * m0x;  m0y = m0y > 0.f ? m0y : NEGSLOPE * m0y;
        m1x = m1x > 0.f ? m1x : NEGSLOPE * m1x;  m1y = m1y > 0.f ? m1y : NEGSLOPE * m1y;
        m2x = m2x > 0.f ? m2x : NEGSLOPE * m2x;  m2y = m2y > 0.f ? m2y : NEGSLOPE * m2y;
        m3x = m3x > 0.f ? m3x : NEGSLOPE * m3x;  m3y = m3y > 0.f ? m3y : NEGSLOPE * m3y;
        float p0 = m0x * av.x + m0y * av.y;
        float p1 = m1x * av.x + m1y * av.y;
        float p2 = m2x * av.x + m2y * av.y;
        float p3 = m3x * av.x + m3y * av.y;
        p0 += __shfl_xor_sync(0xffffffffu, p0, 1);
        p1 += __shfl_xor_sync(0xffffffffu, p1, 1);
        p2 += __shfl_xor_sync(0xffffffffu, p2, 1);
        p3 += __shfl_xor_sync(0xffffffffu, p3, 1);
        p0 += __shfl_xor_sync(0xffffffffu, p0, 2);
        p1 += __shfl_xor_sync(0xffffffffu, p1, 2);
        p2 += __shfl_xor_sync(0xffffffffu, p2, 2);
        p3 += __shfl_xor_sync(0xffffffffu, p3, 2);
        p0 += __shfl_xor_sync(0xffffffffu, p0, 4);
        p1 += __shfl_xor_sync(0xffffffffu, p1, 4);
        p2 += __shfl_xor_sync(0xffffffffu, p2, 4);
        p3 += __shfl_xor_sync(0xffffffffu, p3, 4);
        float e0 = __expf(p0), e1 = __expf(p1), e2 = __expf(p2), e3 = __expf(p3);
        if ((lane & 7) == 0) {
            ((float*)&g_sc[pos    ])[head] = e0;
            ((float*)&g_sc[pos + 1])[head] = e1;
            ((float*)&g_sc[pos + 2])[head] = e2;
            ((float*)&g_sc[pos + 3])[head] = e3;
        }
        den0 += e0 + e1;
        den1 += e2 + e3;
        acc0.x = fmaf(e0, x0.x, acc0.x);  acc0.y = fmaf(e0, x0.y, acc0.y);
        acc1.x = fmaf(e1, x1.x, acc1.x);  acc1.y = fmaf(e1, x1.y, acc1.y);
        acc0.x = fmaf(e2, x2.x, acc0.x);  acc0.y = fmaf(e2, x2.y, acc0.y);
        acc1.x = fmaf(e3, x3.x, acc1.x);  acc1.y = fmaf(e3, x3.y, acc1.y);
    }
    for (; pos < re; pos++) {
        int2 q = g_pc[pos];
        float2 xlv = *(const float2*)&g_xl[(size_t)q.x * 64 + 2 * lane];
        float mx = xlv.x + xrv.x;
        float my = xlv.y + xrv.y;
        mx = mx > 0.f ? mx : NEGSLOPE * mx;
        my = my > 0.f ? my : NEGSLOPE * my;
        float p = mx * av.x + my * av.y;
        p += __shfl_xor_sync(0xffffffffu, p, 1);
        p += __shfl_xor_sync(0xffffffffu, p, 2);
        p += __shfl_xor_sync(0xffffffffu, p, 4);
        float e = __expf(p);
        if ((lane & 7) == 0) ((float*)&g_sc[pos])[head] = e;
        den0 += e;
        acc0.x = fmaf(e, xlv.x, acc0.x);
        acc0.y = fmaf(e, xlv.y, acc0.y);
    }
    float denom = den0 + den1;
    float2 acc = make_float2(acc0.x + acc1.x, acc0.y + acc1.y);
    float rcp = 1.f / (denom + EPSV);

    float2 bv = ((const float2*)bias)[lane];
    float ox = fmaxf(fmaf(acc.x, rcp, bv.x), 0.f);
    float oy = fmaxf(fmaf(acc.y, rcp, bv.y), 0.f);
    if (out_mode) {
        *(uint2*)&g_hp[(size_t)node * 64 + 2 * lane] = make_uint2(packbf(ox), packbf(oy));
    } else {
        *(float2*)&outext[(size_t)node * 64 + 2 * lane] = make_float2(ox, oy);
    }

    float r0 = __shfl_sync(0xffffffffu, rcp, 0);
    float r1 = __shfl_sync(0xffffffffu, rcp, 8);
    float r2 = __shfl_sync(0xffffffffu, rcp, 16);
    float r3 = __shfl_sync(0xffffffffu, rcp, 24);
    __syncwarp();
    for (int q = rs + lane; q < re; q += 32) {
        float4 e4 = g_sc[q];
        float4 a4 = make_float4(e4.x * r0, e4.y * r1, e4.z * r2, e4.w * r3);
        *(float4*)&alpha[(size_t)g_pc[q].y * 4] = a4;
    }
}

// ---------------- launch ----------------
extern "C" void kernel_launch(void* const* d_in, const int* in_sizes, int n_in,
                              void* d_out, int out_size) {
    const float* x     = (const float*)d_in[0];
    const int*   ei    = (const int*)d_in[1];
    const float* Wl1   = (const float*)d_in[2];
    const float* bl1   = (const float*)d_in[3];
    const float* Wr1   = (const float*)d_in[4];
    const float* br1   = (const float*)d_in[5];
    const float* att1  = (const float*)d_in[6];
    const float* bias1 = (const float*)d_in[7];
    const float* Wl2   = (const float*)d_in[8];
    const float* bl2   = (const float*)d_in[9];
    const float* Wr2   = (const float*)d_in[10];
    const float* br2   = (const float*)d_in[11];
    const float* att2  = (const float*)d_in[12];
    const float* bias2 = (const float*)d_in[13];

    int n    = in_sizes[0] / 128;  // 100000
    int E    = in_sizes[1] / 2;    // 1600000
    int etot = E + n;              // 1700000
    int nb   = (n + SCHUNK - 1) / SCHUNK;

    float* out    = (float*)d_out;
    float* outh   = out;
    float* alpha1 = out + (size_t)n * 64;
    float* alpha2 = alpha1 + (size_t)etot * 4;

    cudaFuncSetAttribute(k_gemm_bf<128>, cudaFuncAttributeMaxDynamicSharedMemorySize, 103424);
    cudaFuncSetAttribute(k_gemm_bf<64>,  cudaFuncAttributeMaxDynamicSharedMemorySize, 52224);

    unsigned* d_xp; cudaGetSymbolAddress((void**)&d_xp, g_xp);
    unsigned* d_hp; cudaGetSymbolAddress((void**)&d_hp, g_hp);
    int* d_cnt;     cudaGetSymbolAddress((void**)&d_cnt, g_cnt);

    // side stream + fork/join events: created once, on the first
    // (uncaptured correctness) call. The captured work is identical per call.
    static cudaStream_t s2 = nullptr;
    static cudaEvent_t evFork = nullptr, evJoin = nullptr;
    if (s2 == nullptr) {
        cudaStreamCreateWithFlags(&s2, cudaStreamNonBlocking);
        cudaEventCreateWithFlags(&evFork, cudaEventDisableTiming);
        cudaEventCreateWithFlags(&evJoin, cudaEventDisableTiming);
    }

    int total4 = n * 128 / 4;

    // fork: CSR build on side stream, pack+GEMM128 on main stream
    cudaEventRecord(evFork, 0);
    cudaStreamWaitEvent(s2, evFork, 0);

    cudaMemsetAsync(d_cnt, 0, (size_t)n * sizeof(int), s2);
    k_count<<<(etot + 511) / 512, 512, 0, s2>>>(ei, E, etot);
    k_scanA<<<nb, SCHUNK, 0, s2>>>(n);
    k_scanB<<<1, 256, 0, s2>>>(nb, n);
    k_scanC<<<nb, SCHUNK, 0, s2>>>(n);
    k_scatter<<<(etot + 511) / 512, 512, 0, s2>>>(ei, E, etot);
    cudaEventRecord(evJoin, s2);

    k_pack<<<(total4 + 511) / 512, 512>>>(x, total4);
    k_gemm_bf<128><<<296, 256, 103424>>>(d_xp, Wl1, bl1, Wr1, br1, n);

    // join: node1 needs xl/xr AND the CSR
    cudaStreamWaitEvent(0, evJoin, 0);

    // layer 1 edge phase (writes packed h)
    k_node<<<(n + 7) / 8, 256>>>(1, nullptr, att1, bias1, alpha1, n);

    // layer 2 (input = packed h)
    k_gemm_bf<64><<<444, 256, 52224>>>(d_hp, Wl2, bl2, Wr2, br2, n);
    k_node<<<(n + 7) / 8, 256>>>(0, outh, att2, bias2, alpha2, n);
}